// round 15
// baseline (speedup 1.0000x reference)
#include <cuda_runtime.h>
#include <cuda_bf16.h>
#include <cuda_fp16.h>
#include <math.h>
#include <stdint.h>

// ---------------- problem constants ----------------
#define BATCH   256
#define RANK    16
#define IN_D    784
#define H1      512
#define OUT_D   10
#define KDIM    128
#define TOTAL   29610
#define TOTAL_PAD 29696          // 232 * 128

// g layout offsets (per sample)
#define O_A1    0
#define O_B1    8192
#define O_BIAS1 20736
#define O_A2    21248
#define O_B2    21408
#define O_BIAS2 29600

// ---------------- scratch ----------------
__device__ __align__(16) float s_conv2[BATCH * 32 * 7 * 7];
__device__ __align__(16) float s_part [8 * BATCH * 64];
__device__ __align__(16) float s_g    [(size_t)BATCH * TOTAL_PAD];
__device__ __align__(16) __half s_g2h[(size_t)TOTAL_PAD * KDIM];   // fp16
__device__ __align__(16) __half s_g1h[BATCH * KDIM];               // fp16

// ================= helpers =================
__device__ __forceinline__ uint32_t smem_u32(const void* p) {
    uint32_t a;
    asm("{ .reg .u64 t; cvta.to.shared.u64 t, %1; cvt.u32.u64 %0, t; }"
        : "=r"(a) : "l"(p));
    return a;
}

__device__ __forceinline__ void ldsm_x4(uint32_t addr, uint32_t* r) {
    asm volatile("ldmatrix.sync.aligned.m8n8.x4.shared.b16 {%0,%1,%2,%3}, [%4];"
        : "=r"(r[0]), "=r"(r[1]), "=r"(r[2]), "=r"(r[3]) : "r"(addr));
}

__device__ __forceinline__ void mma_f16(float* c, const uint32_t* a, const uint32_t* b) {
    asm volatile("mma.sync.aligned.m16n8k16.row.col.f32.f16.f16.f32 "
        "{%0,%1,%2,%3}, {%4,%5,%6,%7}, {%8,%9}, {%0,%1,%2,%3};"
        : "+f"(c[0]), "+f"(c[1]), "+f"(c[2]), "+f"(c[3])
        : "r"(a[0]), "r"(a[1]), "r"(a[2]), "r"(a[3]), "r"(b[0]), "r"(b[1]));
}

#define CP_ASYNC16(dst, src) \
    asm volatile("cp.async.cg.shared.global [%0], [%1], 16;" \
        :: "r"(dst), "l"(src) : "memory")
#define CP_COMMIT() asm volatile("cp.async.commit_group;" ::: "memory")
#define CP_WAIT(n)  asm volatile("cp.async.wait_group %0;" :: "n"(n) : "memory")

// ================= prep: g2w fp32 -> fp16 =================
__global__ void prep_g2w_k(const float* __restrict__ g2w) {
    size_t idx = ((size_t)blockIdx.x * 256 + threadIdx.x) * 8;
    if (idx >= (size_t)TOTAL_PAD * KDIM) return;
    float f[8];
    if (idx < (size_t)TOTAL * KDIM) {
        float4 v0 = *(const float4*)(g2w + idx);
        float4 v1 = *(const float4*)(g2w + idx + 4);
        f[0]=v0.x; f[1]=v0.y; f[2]=v0.z; f[3]=v0.w;
        f[4]=v1.x; f[5]=v1.y; f[6]=v1.z; f[7]=v1.w;
    } else {
#pragma unroll
        for (int i = 0; i < 8; i++) f[i] = 0.f;
    }
    unsigned short hb[8];
#pragma unroll
    for (int i = 0; i < 8; i++) hb[i] = __half_as_ushort(__float2half_rn(f[i]));
    uint4 hi;
    hi.x = (uint32_t)hb[0] | ((uint32_t)hb[1] << 16);
    hi.y = (uint32_t)hb[2] | ((uint32_t)hb[3] << 16);
    hi.z = (uint32_t)hb[4] | ((uint32_t)hb[5] << 16);
    hi.w = (uint32_t)hb[6] | ((uint32_t)hb[7] << 16);
    *(uint4*)(s_g2h + idx) = hi;
}

// ================= conv1+conv2 fused =================
__global__ void conv_fused_k(const float* __restrict__ img,
                             const float* __restrict__ c1w, const float* __restrict__ c1b,
                             const float* __restrict__ c2w, const float* __restrict__ c2b) {
    __shared__ float im[784];
    __shared__ float w1[144];
    __shared__ float h1s[16 * 196];
    __shared__ float w2[4608];
    int b = blockIdx.x;
    int tid = threadIdx.x;

    for (int i = tid; i < 784; i += 256) im[i] = img[b * 784 + i];
    for (int i = tid; i < 144; i += 256) w1[i] = c1w[i];
    for (int i = tid; i < 4608; i += 256) w2[i] = c2w[i];
    __syncthreads();

    for (int idx = tid; idx < 16 * 196; idx += 256) {
        int c = idx / 196, p = idx % 196;
        int y = p / 14, x = p % 14;
        float acc = c1b[c];
        int iy0 = y * 2 - 1, ix0 = x * 2 - 1;
        const float* wp = w1 + c * 9;
#pragma unroll
        for (int ky = 0; ky < 3; ky++) {
            int iy = iy0 + ky;
            if (iy < 0 || iy >= 28) continue;
#pragma unroll
            for (int kx = 0; kx < 3; kx++) {
                int ix = ix0 + kx;
                if (ix < 0 || ix >= 28) continue;
                acc += im[iy * 28 + ix] * wp[ky * 3 + kx];
            }
        }
        h1s[idx] = fmaxf(acc, 0.f);
    }
    __syncthreads();

    for (int idx = tid; idx < 32 * 49; idx += 256) {
        int oc = idx / 49, p = idx % 49;
        int y = p / 7, x = p % 7;
        float acc = c2b[oc];
        int iy0 = y * 2 - 1, ix0 = x * 2 - 1;
#pragma unroll
        for (int ic = 0; ic < 16; ic++) {
            const float* hb = h1s + ic * 196;
            const float* wp = w2 + oc * 144 + ic * 9;
#pragma unroll
            for (int ky = 0; ky < 3; ky++) {
                int iy = iy0 + ky;
                if (iy < 0 || iy >= 14) continue;
#pragma unroll
                for (int kx = 0; kx < 3; kx++) {
                    int ix = ix0 + kx;
                    if (ix < 0 || ix >= 14) continue;
                    acc += hb[iy * 14 + ix] * wp[ky * 3 + kx];
                }
            }
        }
        s_conv2[b * 1568 + idx] = fmaxf(acc, 0.f);
    }
}

// ================= style split-K =================
#define ST_STRIDE 201
#define STYLE_SMEM ((32 * ST_STRIDE + 64 * ST_STRIDE) * 4)
__global__ void style_part_k(const float* __restrict__ sew) {
    extern __shared__ float smf[];
    float* h_sm = smf;
    float* w_sm = smf + 32 * ST_STRIDE;
    int tid = threadIdx.x;
    int b0 = blockIdx.x * 32;
    int kc = blockIdx.y;
    int k0 = kc * 196;

    for (int idx = tid; idx < 32 * 196; idx += 256) {
        int s = idx / 196, i = idx % 196;
        h_sm[s * ST_STRIDE + i] = s_conv2[(b0 + s) * 1568 + k0 + i];
    }
    for (int idx = tid; idx < 64 * 196; idx += 256) {
        int j = idx / 196, i = idx % 196;
        w_sm[j * ST_STRIDE + i] = sew[j * 1568 + k0 + i];
    }
    __syncthreads();

    int to = tid & 31;
    int ts = tid >> 5;
    float acc[4][2] = {};
    const float* h0 = h_sm + (ts * 4 + 0) * ST_STRIDE;
    const float* h1 = h_sm + (ts * 4 + 1) * ST_STRIDE;
    const float* h2 = h_sm + (ts * 4 + 2) * ST_STRIDE;
    const float* h3 = h_sm + (ts * 4 + 3) * ST_STRIDE;
    const float* w0 = w_sm + to * ST_STRIDE;
    const float* w1 = w_sm + (to + 32) * ST_STRIDE;
#pragma unroll 4
    for (int i = 0; i < 196; i++) {
        float wa = w0[i], wb = w1[i];
        float v0 = h0[i], v1 = h1[i], v2 = h2[i], v3 = h3[i];
        acc[0][0] += v0 * wa; acc[0][1] += v0 * wb;
        acc[1][0] += v1 * wa; acc[1][1] += v1 * wb;
        acc[2][0] += v2 * wa; acc[2][1] += v2 * wb;
        acc[3][0] += v3 * wa; acc[3][1] += v3 * wb;
    }
#pragma unroll
    for (int s4 = 0; s4 < 4; s4++) {
        int b = b0 + ts * 4 + s4;
        s_part[(kc * BATCH + b) * 64 + to]      = acc[s4][0];
        s_part[(kc * BATCH + b) * 64 + to + 32] = acc[s4][1];
    }
}

// ================= reduce partials + tanh + g1 -> fp16 ============
#define G1W_STRIDE 65
__global__ void reduce_g1_k(const float* __restrict__ seb,
                            const float* __restrict__ g1w, const float* __restrict__ g1b) {
    __shared__ float wsm[128 * G1W_STRIDE];
    __shared__ float st[2 * 64];
    int tid = threadIdx.x;
    int b0 = blockIdx.x * 2;

#pragma unroll
    for (int i4 = tid; i4 < 2048; i4 += 256) {
        float4 v = ((const float4*)g1w)[i4];
        int o = i4 >> 4, k = (i4 & 15) << 2;
        float* d = wsm + o * G1W_STRIDE + k;
        d[0] = v.x; d[1] = v.y; d[2] = v.z; d[3] = v.w;
    }
    if (tid < 128) {
        int s = tid >> 6, j = tid & 63;
        float acc = seb[j];
#pragma unroll
        for (int kc = 0; kc < 8; kc++)
            acc += s_part[(kc * BATCH + b0 + s) * 64 + j];
        st[s * 64 + j] = tanhf(acc);
    }
    __syncthreads();

    int s = tid >> 7;
    int o = tid & 127;
    float acc = g1b[o];
    const float* wr = wsm + o * G1W_STRIDE;
    const float* sp = st + s * 64;
#pragma unroll 8
    for (int k = 0; k < 64; k++) acc += wr[k] * sp[k];
    float v = fmaxf(acc, 0.f);
    s_g1h[(b0 + s) * KDIM + o] = __float2half_rn(v);
}

// ========== generator GEMM: pure fp16, single product, 3 CTA/SM ==========
// smem: Ahi | Bhi + bias = 70 KB
#define A_STRIDE 136                       // fp16 elems per smem row (272B)
#define AS2      (A_STRIDE * 2)
#define T_BYTES  (128 * AS2)               // 34816
#define OFF_AHI  0
#define OFF_BHI  (T_BYTES)
#define OFF_BIAS (2 * T_BYTES)             // 69632
#define GEMM_SMEM (OFF_BIAS + 512)         // 70144 -> 3 CTAs/SM
#define CS_STRIDE 132

__global__ void __launch_bounds__(256, 3) gemm_hmma_k(const float* __restrict__ g2b) {
    extern __shared__ char sm[];
    uint32_t smb = smem_u32(sm);
    int tid = threadIdx.x;
    int wid = tid >> 5, lane = tid & 31;
    int bm = blockIdx.x * 128;
    int bn = blockIdx.y * 128;

    float* bias_sm = (float*)(sm + OFF_BIAS);

    const char* ah = (const char*)(s_g2h + (size_t)bm * KDIM);
    const char* bh = (const char*)(s_g1h + (size_t)bn * KDIM);

    // ---- cp.async: Ahi + Bhi ----
#pragma unroll
    for (int i = 0; i < 8; i++) {
        int c = tid + i * 256;
        int row = c >> 4, col = c & 15;
        CP_ASYNC16(smb + OFF_AHI + row * AS2 + col * 16, ah + row * 256 + col * 16);
    }
#pragma unroll
    for (int i = 0; i < 8; i++) {
        int c = tid + i * 256;
        int row = c >> 4, col = c & 15;
        CP_ASYNC16(smb + OFF_BHI + row * AS2 + col * 16, bh + row * 256 + col * 16);
    }
    CP_COMMIT();
    if (tid < 128) {
        int m = bm + tid;
        bias_sm[tid] = (m < TOTAL) ? g2b[m] : 0.f;
    }

    // ---- warp layout 4(M) x 2(N); warp tile 32x64 ----
    int wm = (wid & 3) * 32;
    int wn = (wid >> 2) * 64;
    int g = lane >> 3, r = lane & 7;
    int a_row = (g & 1) * 8 + r,  a_kof = (g >> 1) * 8;
    int b_row = (g >> 1) * 8 + r, b_kof = (g & 1) * 8;

    float c[16][4];
#pragma unroll
    for (int i = 0; i < 16; i++)
#pragma unroll
        for (int q = 0; q < 4; q++) c[i][q] = 0.f;

    uint32_t a_hi0 = smb + OFF_AHI + (wm + a_row) * AS2 + a_kof * 2;
    uint32_t b_hi0 = smb + OFF_BHI + (wn + b_row) * AS2 + b_kof * 2;

    CP_WAIT(0);
    __syncthreads();
#pragma unroll
    for (int ks = 0; ks < 8; ks++) {
        uint32_t kbyte = ks * 32;
        uint32_t A0[4], A1[4], B[4][4];
        ldsm_x4(a_hi0 + kbyte, A0);
        ldsm_x4(a_hi0 + 16 * AS2 + kbyte, A1);
#pragma unroll
        for (int nb = 0; nb < 4; nb++)
            ldsm_x4(b_hi0 + nb * 16 * AS2 + kbyte, B[nb]);
#pragma unroll
        for (int nb = 0; nb < 4; nb++) {
            mma_f16(c[nb * 2 + 0],     A0, &B[nb][0]);
            mma_f16(c[nb * 2 + 1],     A0, &B[nb][2]);
            mma_f16(c[8 + nb * 2 + 0], A1, &B[nb][0]);
            mma_f16(c[8 + nb * 2 + 1], A1, &B[nb][2]);
        }
    }
    __syncthreads();   // operands dead; reuse smem as C staging

    // ---- stage C -> smem [n][m] transpose, then coalesced global write ----
    float* Cs = (float*)sm;   // 128 * 132 * 4 = 67.6 KB (fits in 70 KB)
    {
        int mr = lane >> 2;
        int nc = (lane & 3) * 2;
#pragma unroll
        for (int mi = 0; mi < 2; mi++) {
#pragma unroll
            for (int ni = 0; ni < 8; ni++) {
                float* cf = c[mi * 8 + ni];
                int m = wm + mi * 16 + mr;
                int n = wn + ni * 8 + nc;
                Cs[(n)     * CS_STRIDE + m]     = cf[0];
                Cs[(n + 1) * CS_STRIDE + m]     = cf[1];
                Cs[(n)     * CS_STRIDE + m + 8] = cf[2];
                Cs[(n + 1) * CS_STRIDE + m + 8] = cf[3];
            }
        }
    }
    __syncthreads();
    {
        int s  = tid >> 1;
        int mh = (tid & 1) * 64;
        float* dst = s_g + (size_t)(bn + s) * TOTAL_PAD + bm + mh;
        const float* csrc = Cs + s * CS_STRIDE + mh;
        const float* bia  = bias_sm + mh;
#pragma unroll
        for (int i = 0; i < 64; i += 4) {
            float4 v = *(const float4*)(csrc + i);
            v.x += bia[i + 0]; v.y += bia[i + 1];
            v.z += bia[i + 2]; v.w += bia[i + 3];
            *(float4*)(dst + i) = v;
        }
    }
}

// ================= apply: per-sample low-rank MLP (256 threads) ========
__global__ void apply_k(const float* __restrict__ img, float* __restrict__ out) {
    int b = blockIdx.x;
    __shared__ float4 xs4[196];
    __shared__ float h1[H1];
    __shared__ float t1[RANK];
    __shared__ float t2[RANK];
    int tid = threadIdx.x;
    int warp = tid >> 5, lane = tid & 31;
    const float* gb = s_g + (size_t)b * TOTAL_PAD;

    if (tid < 196) xs4[tid] = ((const float4*)(img + b * IN_D))[tid];
    __syncthreads();

    {
        const float4* bp0 = (const float4*)(gb + O_B1 + warp * IN_D);
        const float4* bp1 = (const float4*)(gb + O_B1 + (warp + 8) * IN_D);
        float acc0 = 0.f, acc1 = 0.f;
#pragma unroll 7
        for (int i = lane; i < 196; i += 32) {
            float4 x = xs4[i];
            float4 wA = bp0[i];
            float4 wB = bp1[i];
            acc0 += wA.x * x.x + wA.y * x.y + wA.z * x.z + wA.w * x.w;
            acc1 += wB.x * x.x + wB.y * x.y + wB.z * x.z + wB.w * x.w;
        }
#pragma unroll
        for (int o = 16; o > 0; o >>= 1) {
            acc0 += __shfl_xor_sync(0xffffffffu, acc0, o);
            acc1 += __shfl_xor_sync(0xffffffffu, acc1, o);
        }
        if (lane == 0) { t1[warp] = acc0; t1[warp + 8] = acc1; }
    }
    __syncthreads();

    {
        const float4* tp = (const float4*)t1;
        float4 t0 = tp[0], t1v = tp[1], t2v = tp[2], t3 = tp[3];
#pragma unroll
        for (int q = 0; q < 2; q++) {
            int o = tid + q * 256;
            const float4* ap = (const float4*)(gb + O_A1 + o * RANK);
            float acc = gb[O_BIAS1 + o];
            float4 a0 = ap[0], a1 = ap[1], a2 = ap[2], a3 = ap[3];
            acc += a0.x * t0.x + a0.y * t0.y + a0.z * t0.z + a0.w * t0.w;
            acc += a1.x * t1v.x + a1.y * t1v.y + a1.z * t1v.z + a1.w * t1v.w;
            acc += a2.x * t2v.x + a2.y * t2v.y + a2.z * t2v.z + a2.w * t2v.w;
            acc += a3.x * t3.x + a3.y * t3.y + a3.z * t3.z + a3.w * t3.w;
            h1[o] = fmaxf(acc, 0.f);
        }
    }
    __syncthreads();

    {
        const float4* bp0 = (const float4*)(gb + O_B2 + warp * H1);
        const float4* bp1 = (const float4*)(gb + O_B2 + (warp + 8) * H1);
        const float4* hp = (const float4*)h1;
        float acc0 = 0.f, acc1 = 0.f;
#pragma unroll
        for (int i = lane; i < 128; i += 32) {
            float4 h = hp[i];
            float4 wA = bp0[i];
            float4 wB = bp1[i];
            acc0 += wA.x * h.x + wA.y * h.y + wA.z * h.z + wA.w * h.w;
            acc1 += wB.x * h.x + wB.y * h.y + wB.z * h.z + wB.w * h.w;
        }
#pragma unroll
        for (int o = 16; o > 0; o >>= 1) {
            acc0 += __shfl_xor_sync(0xffffffffu, acc0, o);
            acc1 += __shfl_xor_sync(0xffffffffu, acc1, o);
        }
        if (lane == 0) { t2[warp] = acc0; t2[warp + 8] = acc1; }
    }
    __syncthreads();

    if (tid < OUT_D) {
        const float4* ap = (const float4*)(gb + O_A2 + tid * RANK);
        const float4* tp = (const float4*)t2;
        float acc = gb[O_BIAS2 + tid];
#pragma unroll
        for (int q = 0; q < 4; q++) {
            float4 a = ap[q], t = tp[q];
            acc += a.x * t.x + a.y * t.y + a.z * t.z + a.w * t.w;
        }
        out[b * OUT_D + tid] = acc;
    }
}

// ================= launch =================
extern "C" void kernel_launch(void* const* d_in, const int* in_sizes, int n_in,
                              void* d_out, int out_size) {
    const float* images = (const float*)d_in[0];
    const float* c1w    = (const float*)d_in[1];
    const float* c1b    = (const float*)d_in[2];
    const float* c2w    = (const float*)d_in[3];
    const float* c2b    = (const float*)d_in[4];
    const float* sew    = (const float*)d_in[5];
    const float* seb    = (const float*)d_in[6];
    const float* g1w    = (const float*)d_in[7];
    const float* g1b    = (const float*)d_in[8];
    const float* g2w    = (const float*)d_in[9];
    const float* g2b    = (const float*)d_in[10];
    float* out = (float*)d_out;

    cudaFuncSetAttribute(style_part_k, cudaFuncAttributeMaxDynamicSharedMemorySize,
                         STYLE_SMEM);
    cudaFuncSetAttribute(gemm_hmma_k, cudaFuncAttributeMaxDynamicSharedMemorySize,
                         GEMM_SMEM);

    prep_g2w_k<<<(TOTAL_PAD * KDIM / 8 + 255) / 256, 256>>>(g2w);
    conv_fused_k<<<BATCH, 256>>>(images, c1w, c1b, c2w, c2b);
    style_part_k<<<dim3(8, 8), 256, STYLE_SMEM>>>(sew);
    reduce_g1_k<<<BATCH / 2, 256>>>(seb, g1w, g1b);
    gemm_hmma_k<<<dim3(TOTAL_PAD / 128, BATCH / 128), 256, GEMM_SMEM>>>(g2b);
    apply_k<<<BATCH, 256>>>(images, out);
}

// round 16
// speedup vs baseline: 1.3174x; 1.3174x over previous
#include <cuda_runtime.h>
#include <cuda_bf16.h>
#include <cuda_fp16.h>
#include <math.h>
#include <stdint.h>

// ---------------- problem constants ----------------
#define BATCH   256
#define RANK    16
#define IN_D    784
#define H1      512
#define OUT_D   10
#define KDIM    128
#define TOTAL   29610
#define TOTAL_PAD 29696          // 232 * 128

// g layout offsets (per sample)
#define O_A1    0
#define O_B1    8192
#define O_BIAS1 20736
#define O_A2    21248
#define O_B2    21408
#define O_BIAS2 29600

// ---------------- scratch ----------------
__device__ __align__(16) float s_conv2[BATCH * 32 * 7 * 7];
__device__ __align__(16) float s_part [8 * BATCH * 64];
__device__ __align__(16) float s_g    [(size_t)BATCH * TOTAL_PAD];
__device__ __align__(16) __half s_g2h[(size_t)TOTAL_PAD * KDIM];   // fp16
__device__ __align__(16) __half s_g1h[BATCH * KDIM];               // fp16

// ================= helpers =================
__device__ __forceinline__ uint32_t smem_u32(const void* p) {
    uint32_t a;
    asm("{ .reg .u64 t; cvta.to.shared.u64 t, %1; cvt.u32.u64 %0, t; }"
        : "=r"(a) : "l"(p));
    return a;
}

__device__ __forceinline__ void ldsm_x4(uint32_t addr, uint32_t* r) {
    asm volatile("ldmatrix.sync.aligned.m8n8.x4.shared.b16 {%0,%1,%2,%3}, [%4];"
        : "=r"(r[0]), "=r"(r[1]), "=r"(r[2]), "=r"(r[3]) : "r"(addr));
}

__device__ __forceinline__ void mma_f16(float* c, const uint32_t* a, const uint32_t* b) {
    asm volatile("mma.sync.aligned.m16n8k16.row.col.f32.f16.f16.f32 "
        "{%0,%1,%2,%3}, {%4,%5,%6,%7}, {%8,%9}, {%0,%1,%2,%3};"
        : "+f"(c[0]), "+f"(c[1]), "+f"(c[2]), "+f"(c[3])
        : "r"(a[0]), "r"(a[1]), "r"(a[2]), "r"(a[3]), "r"(b[0]), "r"(b[1]));
}

#define CP_ASYNC16(dst, src) \
    asm volatile("cp.async.cg.shared.global [%0], [%1], 16;" \
        :: "r"(dst), "l"(src) : "memory")
#define CP_COMMIT() asm volatile("cp.async.commit_group;" ::: "memory")
#define CP_WAIT(n)  asm volatile("cp.async.wait_group %0;" :: "n"(n) : "memory")

// ================= prep: g2w fp32 -> fp16 =================
__global__ void prep_g2w_k(const float* __restrict__ g2w) {
    size_t idx = ((size_t)blockIdx.x * 256 + threadIdx.x) * 8;
    if (idx >= (size_t)TOTAL_PAD * KDIM) return;
    float f[8];
    if (idx < (size_t)TOTAL * KDIM) {
        float4 v0 = *(const float4*)(g2w + idx);
        float4 v1 = *(const float4*)(g2w + idx + 4);
        f[0]=v0.x; f[1]=v0.y; f[2]=v0.z; f[3]=v0.w;
        f[4]=v1.x; f[5]=v1.y; f[6]=v1.z; f[7]=v1.w;
    } else {
#pragma unroll
        for (int i = 0; i < 8; i++) f[i] = 0.f;
    }
    unsigned short hb[8];
#pragma unroll
    for (int i = 0; i < 8; i++) hb[i] = __half_as_ushort(__float2half_rn(f[i]));
    uint4 hi;
    hi.x = (uint32_t)hb[0] | ((uint32_t)hb[1] << 16);
    hi.y = (uint32_t)hb[2] | ((uint32_t)hb[3] << 16);
    hi.z = (uint32_t)hb[4] | ((uint32_t)hb[5] << 16);
    hi.w = (uint32_t)hb[6] | ((uint32_t)hb[7] << 16);
    *(uint4*)(s_g2h + idx) = hi;
}

// ================= conv1+conv2 fused =================
__global__ void conv_fused_k(const float* __restrict__ img,
                             const float* __restrict__ c1w, const float* __restrict__ c1b,
                             const float* __restrict__ c2w, const float* __restrict__ c2b) {
    __shared__ float im[784];
    __shared__ float w1[144];
    __shared__ float h1s[16 * 196];
    __shared__ float w2[4608];
    int b = blockIdx.x;
    int tid = threadIdx.x;

    for (int i = tid; i < 784; i += 256) im[i] = img[b * 784 + i];
    for (int i = tid; i < 144; i += 256) w1[i] = c1w[i];
    for (int i = tid; i < 4608; i += 256) w2[i] = c2w[i];
    __syncthreads();

    for (int idx = tid; idx < 16 * 196; idx += 256) {
        int c = idx / 196, p = idx % 196;
        int y = p / 14, x = p % 14;
        float acc = c1b[c];
        int iy0 = y * 2 - 1, ix0 = x * 2 - 1;
        const float* wp = w1 + c * 9;
#pragma unroll
        for (int ky = 0; ky < 3; ky++) {
            int iy = iy0 + ky;
            if (iy < 0 || iy >= 28) continue;
#pragma unroll
            for (int kx = 0; kx < 3; kx++) {
                int ix = ix0 + kx;
                if (ix < 0 || ix >= 28) continue;
                acc += im[iy * 28 + ix] * wp[ky * 3 + kx];
            }
        }
        h1s[idx] = fmaxf(acc, 0.f);
    }
    __syncthreads();

    for (int idx = tid; idx < 32 * 49; idx += 256) {
        int oc = idx / 49, p = idx % 49;
        int y = p / 7, x = p % 7;
        float acc = c2b[oc];
        int iy0 = y * 2 - 1, ix0 = x * 2 - 1;
#pragma unroll
        for (int ic = 0; ic < 16; ic++) {
            const float* hb = h1s + ic * 196;
            const float* wp = w2 + oc * 144 + ic * 9;
#pragma unroll
            for (int ky = 0; ky < 3; ky++) {
                int iy = iy0 + ky;
                if (iy < 0 || iy >= 14) continue;
#pragma unroll
                for (int kx = 0; kx < 3; kx++) {
                    int ix = ix0 + kx;
                    if (ix < 0 || ix >= 14) continue;
                    acc += hb[iy * 14 + ix] * wp[ky * 3 + kx];
                }
            }
        }
        s_conv2[b * 1568 + idx] = fmaxf(acc, 0.f);
    }
}

// ================= style split-K =================
#define ST_STRIDE 201
#define STYLE_SMEM ((32 * ST_STRIDE + 64 * ST_STRIDE) * 4)
__global__ void style_part_k(const float* __restrict__ sew) {
    extern __shared__ float smf[];
    float* h_sm = smf;
    float* w_sm = smf + 32 * ST_STRIDE;
    int tid = threadIdx.x;
    int b0 = blockIdx.x * 32;
    int kc = blockIdx.y;
    int k0 = kc * 196;

    for (int idx = tid; idx < 32 * 196; idx += 256) {
        int s = idx / 196, i = idx % 196;
        h_sm[s * ST_STRIDE + i] = s_conv2[(b0 + s) * 1568 + k0 + i];
    }
    for (int idx = tid; idx < 64 * 196; idx += 256) {
        int j = idx / 196, i = idx % 196;
        w_sm[j * ST_STRIDE + i] = sew[j * 1568 + k0 + i];
    }
    __syncthreads();

    int to = tid & 31;
    int ts = tid >> 5;
    float acc[4][2] = {};
    const float* h0 = h_sm + (ts * 4 + 0) * ST_STRIDE;
    const float* h1 = h_sm + (ts * 4 + 1) * ST_STRIDE;
    const float* h2 = h_sm + (ts * 4 + 2) * ST_STRIDE;
    const float* h3 = h_sm + (ts * 4 + 3) * ST_STRIDE;
    const float* w0 = w_sm + to * ST_STRIDE;
    const float* w1 = w_sm + (to + 32) * ST_STRIDE;
#pragma unroll 4
    for (int i = 0; i < 196; i++) {
        float wa = w0[i], wb = w1[i];
        float v0 = h0[i], v1 = h1[i], v2 = h2[i], v3 = h3[i];
        acc[0][0] += v0 * wa; acc[0][1] += v0 * wb;
        acc[1][0] += v1 * wa; acc[1][1] += v1 * wb;
        acc[2][0] += v2 * wa; acc[2][1] += v2 * wb;
        acc[3][0] += v3 * wa; acc[3][1] += v3 * wb;
    }
#pragma unroll
    for (int s4 = 0; s4 < 4; s4++) {
        int b = b0 + ts * 4 + s4;
        s_part[(kc * BATCH + b) * 64 + to]      = acc[s4][0];
        s_part[(kc * BATCH + b) * 64 + to + 32] = acc[s4][1];
    }
}

// ================= reduce partials + tanh + g1 -> fp16 ============
#define G1W_STRIDE 65
__global__ void reduce_g1_k(const float* __restrict__ seb,
                            const float* __restrict__ g1w, const float* __restrict__ g1b) {
    __shared__ float wsm[128 * G1W_STRIDE];
    __shared__ float st[2 * 64];
    int tid = threadIdx.x;
    int b0 = blockIdx.x * 2;

#pragma unroll
    for (int i4 = tid; i4 < 2048; i4 += 256) {
        float4 v = ((const float4*)g1w)[i4];
        int o = i4 >> 4, k = (i4 & 15) << 2;
        float* d = wsm + o * G1W_STRIDE + k;
        d[0] = v.x; d[1] = v.y; d[2] = v.z; d[3] = v.w;
    }
    if (tid < 128) {
        int s = tid >> 6, j = tid & 63;
        float acc = seb[j];
#pragma unroll
        for (int kc = 0; kc < 8; kc++)
            acc += s_part[(kc * BATCH + b0 + s) * 64 + j];
        st[s * 64 + j] = tanhf(acc);
    }
    __syncthreads();

    int s = tid >> 7;
    int o = tid & 127;
    float acc = g1b[o];
    const float* wr = wsm + o * G1W_STRIDE;
    const float* sp = st + s * 64;
#pragma unroll 8
    for (int k = 0; k < 64; k++) acc += wr[k] * sp[k];
    float v = fmaxf(acc, 0.f);
    s_g1h[(b0 + s) * KDIM + o] = __float2half_rn(v);
}

// ========== generator GEMM: pure fp16, single product, 2 CTA/SM ==========
// smem: Ahi | Bhi + bias = 70 KB; launch_bounds(256,2) -> 128-reg budget, no spill
#define A_STRIDE 136                       // fp16 elems per smem row (272B)
#define AS2      (A_STRIDE * 2)
#define T_BYTES  (128 * AS2)               // 34816
#define OFF_AHI  0
#define OFF_BHI  (T_BYTES)
#define OFF_BIAS (2 * T_BYTES)             // 69632
#define GEMM_SMEM (OFF_BIAS + 512)         // 70144
#define CS_STRIDE 132

__global__ void __launch_bounds__(256, 2) gemm_hmma_k(const float* __restrict__ g2b) {
    extern __shared__ char sm[];
    uint32_t smb = smem_u32(sm);
    int tid = threadIdx.x;
    int wid = tid >> 5, lane = tid & 31;
    int bm = blockIdx.x * 128;
    int bn = blockIdx.y * 128;

    float* bias_sm = (float*)(sm + OFF_BIAS);

    const char* ah = (const char*)(s_g2h + (size_t)bm * KDIM);
    const char* bh = (const char*)(s_g1h + (size_t)bn * KDIM);

    // ---- cp.async: Ahi + Bhi ----
#pragma unroll
    for (int i = 0; i < 8; i++) {
        int c = tid + i * 256;
        int row = c >> 4, col = c & 15;
        CP_ASYNC16(smb + OFF_AHI + row * AS2 + col * 16, ah + row * 256 + col * 16);
    }
#pragma unroll
    for (int i = 0; i < 8; i++) {
        int c = tid + i * 256;
        int row = c >> 4, col = c & 15;
        CP_ASYNC16(smb + OFF_BHI + row * AS2 + col * 16, bh + row * 256 + col * 16);
    }
    CP_COMMIT();
    if (tid < 128) {
        int m = bm + tid;
        bias_sm[tid] = (m < TOTAL) ? g2b[m] : 0.f;
    }

    // ---- warp layout 4(M) x 2(N); warp tile 32x64 ----
    int wm = (wid & 3) * 32;
    int wn = (wid >> 2) * 64;
    int g = lane >> 3, r = lane & 7;
    int a_row = (g & 1) * 8 + r,  a_kof = (g >> 1) * 8;
    int b_row = (g >> 1) * 8 + r, b_kof = (g & 1) * 8;

    float c[16][4];
#pragma unroll
    for (int i = 0; i < 16; i++)
#pragma unroll
        for (int q = 0; q < 4; q++) c[i][q] = 0.f;

    uint32_t a_hi0 = smb + OFF_AHI + (wm + a_row) * AS2 + a_kof * 2;
    uint32_t b_hi0 = smb + OFF_BHI + (wn + b_row) * AS2 + b_kof * 2;

    CP_WAIT(0);
    __syncthreads();
#pragma unroll
    for (int ks = 0; ks < 8; ks++) {
        uint32_t kbyte = ks * 32;
        uint32_t A0[4], A1[4], B[4][4];
        ldsm_x4(a_hi0 + kbyte, A0);
        ldsm_x4(a_hi0 + 16 * AS2 + kbyte, A1);
#pragma unroll
        for (int nb = 0; nb < 4; nb++)
            ldsm_x4(b_hi0 + nb * 16 * AS2 + kbyte, B[nb]);
#pragma unroll
        for (int nb = 0; nb < 4; nb++) {
            mma_f16(c[nb * 2 + 0],     A0, &B[nb][0]);
            mma_f16(c[nb * 2 + 1],     A0, &B[nb][2]);
            mma_f16(c[8 + nb * 2 + 0], A1, &B[nb][0]);
            mma_f16(c[8 + nb * 2 + 1], A1, &B[nb][2]);
        }
    }
    __syncthreads();   // operands dead; reuse smem as C staging

    // ---- stage C -> smem [n][m] transpose, then coalesced global write ----
    float* Cs = (float*)sm;   // 128 * 132 * 4 = 67.6 KB (fits in 70 KB)
    {
        int mr = lane >> 2;
        int nc = (lane & 3) * 2;
#pragma unroll
        for (int mi = 0; mi < 2; mi++) {
#pragma unroll
            for (int ni = 0; ni < 8; ni++) {
                float* cf = c[mi * 8 + ni];
                int m = wm + mi * 16 + mr;
                int n = wn + ni * 8 + nc;
                Cs[(n)     * CS_STRIDE + m]     = cf[0];
                Cs[(n + 1) * CS_STRIDE + m]     = cf[1];
                Cs[(n)     * CS_STRIDE + m + 8] = cf[2];
                Cs[(n + 1) * CS_STRIDE + m + 8] = cf[3];
            }
        }
    }
    __syncthreads();
    {
        int s  = tid >> 1;
        int mh = (tid & 1) * 64;
        float* dst = s_g + (size_t)(bn + s) * TOTAL_PAD + bm + mh;
        const float* csrc = Cs + s * CS_STRIDE + mh;
        const float* bia  = bias_sm + mh;
#pragma unroll
        for (int i = 0; i < 64; i += 4) {
            float4 v = *(const float4*)(csrc + i);
            v.x += bia[i + 0]; v.y += bia[i + 1];
            v.z += bia[i + 2]; v.w += bia[i + 3];
            *(float4*)(dst + i) = v;
        }
    }
}

// ================= apply: per-sample low-rank MLP (256 threads) ========
__global__ void apply_k(const float* __restrict__ img, float* __restrict__ out) {
    int b = blockIdx.x;
    __shared__ float4 xs4[196];
    __shared__ float h1[H1];
    __shared__ float t1[RANK];
    __shared__ float t2[RANK];
    int tid = threadIdx.x;
    int warp = tid >> 5, lane = tid & 31;
    const float* gb = s_g + (size_t)b * TOTAL_PAD;

    if (tid < 196) xs4[tid] = ((const float4*)(img + b * IN_D))[tid];
    __syncthreads();

    {
        const float4* bp0 = (const float4*)(gb + O_B1 + warp * IN_D);
        const float4* bp1 = (const float4*)(gb + O_B1 + (warp + 8) * IN_D);
        float acc0 = 0.f, acc1 = 0.f;
#pragma unroll 7
        for (int i = lane; i < 196; i += 32) {
            float4 x = xs4[i];
            float4 wA = bp0[i];
            float4 wB = bp1[i];
            acc0 += wA.x * x.x + wA.y * x.y + wA.z * x.z + wA.w * x.w;
            acc1 += wB.x * x.x + wB.y * x.y + wB.z * x.z + wB.w * x.w;
        }
#pragma unroll
        for (int o = 16; o > 0; o >>= 1) {
            acc0 += __shfl_xor_sync(0xffffffffu, acc0, o);
            acc1 += __shfl_xor_sync(0xffffffffu, acc1, o);
        }
        if (lane == 0) { t1[warp] = acc0; t1[warp + 8] = acc1; }
    }
    __syncthreads();

    {
        const float4* tp = (const float4*)t1;
        float4 t0 = tp[0], t1v = tp[1], t2v = tp[2], t3 = tp[3];
#pragma unroll
        for (int q = 0; q < 2; q++) {
            int o = tid + q * 256;
            const float4* ap = (const float4*)(gb + O_A1 + o * RANK);
            float acc = gb[O_BIAS1 + o];
            float4 a0 = ap[0], a1 = ap[1], a2 = ap[2], a3 = ap[3];
            acc += a0.x * t0.x + a0.y * t0.y + a0.z * t0.z + a0.w * t0.w;
            acc += a1.x * t1v.x + a1.y * t1v.y + a1.z * t1v.z + a1.w * t1v.w;
            acc += a2.x * t2v.x + a2.y * t2v.y + a2.z * t2v.z + a2.w * t2v.w;
            acc += a3.x * t3.x + a3.y * t3.y + a3.z * t3.z + a3.w * t3.w;
            h1[o] = fmaxf(acc, 0.f);
        }
    }
    __syncthreads();

    {
        const float4* bp0 = (const float4*)(gb + O_B2 + warp * H1);
        const float4* bp1 = (const float4*)(gb + O_B2 + (warp + 8) * H1);
        const float4* hp = (const float4*)h1;
        float acc0 = 0.f, acc1 = 0.f;
#pragma unroll
        for (int i = lane; i < 128; i += 32) {
            float4 h = hp[i];
            float4 wA = bp0[i];
            float4 wB = bp1[i];
            acc0 += wA.x * h.x + wA.y * h.y + wA.z * h.z + wA.w * h.w;
            acc1 += wB.x * h.x + wB.y * h.y + wB.z * h.z + wB.w * h.w;
        }
#pragma unroll
        for (int o = 16; o > 0; o >>= 1) {
            acc0 += __shfl_xor_sync(0xffffffffu, acc0, o);
            acc1 += __shfl_xor_sync(0xffffffffu, acc1, o);
        }
        if (lane == 0) { t2[warp] = acc0; t2[warp + 8] = acc1; }
    }
    __syncthreads();

    if (tid < OUT_D) {
        const float4* ap = (const float4*)(gb + O_A2 + tid * RANK);
        const float4* tp = (const float4*)t2;
        float acc = gb[O_BIAS2 + tid];
#pragma unroll
        for (int q = 0; q < 4; q++) {
            float4 a = ap[q], t = tp[q];
            acc += a.x * t.x + a.y * t.y + a.z * t.z + a.w * t.w;
        }
        out[b * OUT_D + tid] = acc;
    }
}

// ================= launch =================
extern "C" void kernel_launch(void* const* d_in, const int* in_sizes, int n_in,
                              void* d_out, int out_size) {
    const float* images = (const float*)d_in[0];
    const float* c1w    = (const float*)d_in[1];
    const float* c1b    = (const float*)d_in[2];
    const float* c2w    = (const float*)d_in[3];
    const float* c2b    = (const float*)d_in[4];
    const float* sew    = (const float*)d_in[5];
    const float* seb    = (const float*)d_in[6];
    const float* g1w    = (const float*)d_in[7];
    const float* g1b    = (const float*)d_in[8];
    const float* g2w    = (const float*)d_in[9];
    const float* g2b    = (const float*)d_in[10];
    float* out = (float*)d_out;

    cudaFuncSetAttribute(style_part_k, cudaFuncAttributeMaxDynamicSharedMemorySize,
                         STYLE_SMEM);
    cudaFuncSetAttribute(gemm_hmma_k, cudaFuncAttributeMaxDynamicSharedMemorySize,
                         GEMM_SMEM);

    prep_g2w_k<<<(TOTAL_PAD * KDIM / 8 + 255) / 256, 256>>>(g2w);
    conv_fused_k<<<BATCH, 256>>>(images, c1w, c1b, c2w, c2b);
    style_part_k<<<dim3(8, 8), 256, STYLE_SMEM>>>(sew);
    reduce_g1_k<<<BATCH / 2, 256>>>(seb, g1w, g1b);
    gemm_hmma_k<<<dim3(TOTAL_PAD / 128, BATCH / 128), 256, GEMM_SMEM>>>(g2b);
    apply_k<<<BATCH, 256>>>(images, out);
}

// round 17
// speedup vs baseline: 1.3556x; 1.0290x over previous
#include <cuda_runtime.h>
#include <cuda_bf16.h>
#include <cuda_fp16.h>
#include <math.h>
#include <stdint.h>

// ---------------- problem constants ----------------
#define BATCH   256
#define RANK    16
#define IN_D    784
#define H1      512
#define OUT_D   10
#define KDIM    128
#define TOTAL   29610
#define TOTAL_PAD 29696          // 232 * 128

// g layout offsets (per sample)
#define O_A1    0
#define O_B1    8192
#define O_BIAS1 20736
#define O_A2    21248
#define O_B2    21408
#define O_BIAS2 29600

// ---------------- scratch ----------------
__device__ __align__(16) float s_conv2[BATCH * 32 * 7 * 7];
__device__ __align__(16) float s_part [8 * BATCH * 64];
__device__ __align__(16) __half s_g   [(size_t)BATCH * TOTAL_PAD];  // fp16 now (15 MB)
__device__ __align__(16) __half s_g2h[(size_t)TOTAL_PAD * KDIM];
__device__ __align__(16) __half s_g1h[BATCH * KDIM];

// ================= helpers =================
__device__ __forceinline__ uint32_t smem_u32(const void* p) {
    uint32_t a;
    asm("{ .reg .u64 t; cvta.to.shared.u64 t, %1; cvt.u32.u64 %0, t; }"
        : "=r"(a) : "l"(p));
    return a;
}

__device__ __forceinline__ void ldsm_x4(uint32_t addr, uint32_t* r) {
    asm volatile("ldmatrix.sync.aligned.m8n8.x4.shared.b16 {%0,%1,%2,%3}, [%4];"
        : "=r"(r[0]), "=r"(r[1]), "=r"(r[2]), "=r"(r[3]) : "r"(addr));
}

__device__ __forceinline__ void mma_f16(float* c, const uint32_t* a, const uint32_t* b) {
    asm volatile("mma.sync.aligned.m16n8k16.row.col.f32.f16.f16.f32 "
        "{%0,%1,%2,%3}, {%4,%5,%6,%7}, {%8,%9}, {%0,%1,%2,%3};"
        : "+f"(c[0]), "+f"(c[1]), "+f"(c[2]), "+f"(c[3])
        : "r"(a[0]), "r"(a[1]), "r"(a[2]), "r"(a[3]), "r"(b[0]), "r"(b[1]));
}

#define CP_ASYNC16(dst, src) \
    asm volatile("cp.async.cg.shared.global [%0], [%1], 16;" \
        :: "r"(dst), "l"(src) : "memory")
#define CP_COMMIT() asm volatile("cp.async.commit_group;" ::: "memory")
#define CP_WAIT(n)  asm volatile("cp.async.wait_group %0;" :: "n"(n) : "memory")

// 4 halves -> float4
__device__ __forceinline__ float4 h4_to_f4(uint2 u) {
    float2 lo = __half22float2(*(__half2*)&u.x);
    float2 hi = __half22float2(*(__half2*)&u.y);
    return make_float4(lo.x, lo.y, hi.x, hi.y);
}

// ================= prep: g2w fp32 -> fp16 =================
__global__ void prep_g2w_k(const float* __restrict__ g2w) {
    size_t idx = ((size_t)blockIdx.x * 256 + threadIdx.x) * 8;
    if (idx >= (size_t)TOTAL_PAD * KDIM) return;
    float f[8];
    if (idx < (size_t)TOTAL * KDIM) {
        float4 v0 = *(const float4*)(g2w + idx);
        float4 v1 = *(const float4*)(g2w + idx + 4);
        f[0]=v0.x; f[1]=v0.y; f[2]=v0.z; f[3]=v0.w;
        f[4]=v1.x; f[5]=v1.y; f[6]=v1.z; f[7]=v1.w;
    } else {
#pragma unroll
        for (int i = 0; i < 8; i++) f[i] = 0.f;
    }
    unsigned short hb[8];
#pragma unroll
    for (int i = 0; i < 8; i++) hb[i] = __half_as_ushort(__float2half_rn(f[i]));
    uint4 hi;
    hi.x = (uint32_t)hb[0] | ((uint32_t)hb[1] << 16);
    hi.y = (uint32_t)hb[2] | ((uint32_t)hb[3] << 16);
    hi.z = (uint32_t)hb[4] | ((uint32_t)hb[5] << 16);
    hi.w = (uint32_t)hb[6] | ((uint32_t)hb[7] << 16);
    *(uint4*)(s_g2h + idx) = hi;
}

// ================= conv1+conv2 fused =================
__global__ void conv_fused_k(const float* __restrict__ img,
                             const float* __restrict__ c1w, const float* __restrict__ c1b,
                             const float* __restrict__ c2w, const float* __restrict__ c2b) {
    __shared__ float im[784];
    __shared__ float w1[144];
    __shared__ float h1s[16 * 196];
    __shared__ float w2[4608];
    int b = blockIdx.x;
    int tid = threadIdx.x;

    for (int i = tid; i < 784; i += 256) im[i] = img[b * 784 + i];
    for (int i = tid; i < 144; i += 256) w1[i] = c1w[i];
    for (int i = tid; i < 4608; i += 256) w2[i] = c2w[i];
    __syncthreads();

    for (int idx = tid; idx < 16 * 196; idx += 256) {
        int c = idx / 196, p = idx % 196;
        int y = p / 14, x = p % 14;
        float acc = c1b[c];
        int iy0 = y * 2 - 1, ix0 = x * 2 - 1;
        const float* wp = w1 + c * 9;
#pragma unroll
        for (int ky = 0; ky < 3; ky++) {
            int iy = iy0 + ky;
            if (iy < 0 || iy >= 28) continue;
#pragma unroll
            for (int kx = 0; kx < 3; kx++) {
                int ix = ix0 + kx;
                if (ix < 0 || ix >= 28) continue;
                acc += im[iy * 28 + ix] * wp[ky * 3 + kx];
            }
        }
        h1s[idx] = fmaxf(acc, 0.f);
    }
    __syncthreads();

    for (int idx = tid; idx < 32 * 49; idx += 256) {
        int oc = idx / 49, p = idx % 49;
        int y = p / 7, x = p % 7;
        float acc = c2b[oc];
        int iy0 = y * 2 - 1, ix0 = x * 2 - 1;
#pragma unroll
        for (int ic = 0; ic < 16; ic++) {
            const float* hb = h1s + ic * 196;
            const float* wp = w2 + oc * 144 + ic * 9;
#pragma unroll
            for (int ky = 0; ky < 3; ky++) {
                int iy = iy0 + ky;
                if (iy < 0 || iy >= 14) continue;
#pragma unroll
                for (int kx = 0; kx < 3; kx++) {
                    int ix = ix0 + kx;
                    if (ix < 0 || ix >= 14) continue;
                    acc += hb[iy * 14 + ix] * wp[ky * 3 + kx];
                }
            }
        }
        s_conv2[b * 1568 + idx] = fmaxf(acc, 0.f);
    }
}

// ================= style split-K =================
#define ST_STRIDE 201
#define STYLE_SMEM ((32 * ST_STRIDE + 64 * ST_STRIDE) * 4)
__global__ void style_part_k(const float* __restrict__ sew) {
    extern __shared__ float smf[];
    float* h_sm = smf;
    float* w_sm = smf + 32 * ST_STRIDE;
    int tid = threadIdx.x;
    int b0 = blockIdx.x * 32;
    int kc = blockIdx.y;
    int k0 = kc * 196;

    for (int idx = tid; idx < 32 * 196; idx += 256) {
        int s = idx / 196, i = idx % 196;
        h_sm[s * ST_STRIDE + i] = s_conv2[(b0 + s) * 1568 + k0 + i];
    }
    for (int idx = tid; idx < 64 * 196; idx += 256) {
        int j = idx / 196, i = idx % 196;
        w_sm[j * ST_STRIDE + i] = sew[j * 1568 + k0 + i];
    }
    __syncthreads();

    int to = tid & 31;
    int ts = tid >> 5;
    float acc[4][2] = {};
    const float* h0 = h_sm + (ts * 4 + 0) * ST_STRIDE;
    const float* h1 = h_sm + (ts * 4 + 1) * ST_STRIDE;
    const float* h2 = h_sm + (ts * 4 + 2) * ST_STRIDE;
    const float* h3 = h_sm + (ts * 4 + 3) * ST_STRIDE;
    const float* w0 = w_sm + to * ST_STRIDE;
    const float* w1 = w_sm + (to + 32) * ST_STRIDE;
#pragma unroll 4
    for (int i = 0; i < 196; i++) {
        float wa = w0[i], wb = w1[i];
        float v0 = h0[i], v1 = h1[i], v2 = h2[i], v3 = h3[i];
        acc[0][0] += v0 * wa; acc[0][1] += v0 * wb;
        acc[1][0] += v1 * wa; acc[1][1] += v1 * wb;
        acc[2][0] += v2 * wa; acc[2][1] += v2 * wb;
        acc[3][0] += v3 * wa; acc[3][1] += v3 * wb;
    }
#pragma unroll
    for (int s4 = 0; s4 < 4; s4++) {
        int b = b0 + ts * 4 + s4;
        s_part[(kc * BATCH + b) * 64 + to]      = acc[s4][0];
        s_part[(kc * BATCH + b) * 64 + to + 32] = acc[s4][1];
    }
}

// ================= reduce partials + tanh + g1 -> fp16 ============
#define G1W_STRIDE 65
__global__ void reduce_g1_k(const float* __restrict__ seb,
                            const float* __restrict__ g1w, const float* __restrict__ g1b) {
    __shared__ float wsm[128 * G1W_STRIDE];
    __shared__ float st[2 * 64];
    int tid = threadIdx.x;
    int b0 = blockIdx.x * 2;

#pragma unroll
    for (int i4 = tid; i4 < 2048; i4 += 256) {
        float4 v = ((const float4*)g1w)[i4];
        int o = i4 >> 4, k = (i4 & 15) << 2;
        float* d = wsm + o * G1W_STRIDE + k;
        d[0] = v.x; d[1] = v.y; d[2] = v.z; d[3] = v.w;
    }
    if (tid < 128) {
        int s = tid >> 6, j = tid & 63;
        float acc = seb[j];
#pragma unroll
        for (int kc = 0; kc < 8; kc++)
            acc += s_part[(kc * BATCH + b0 + s) * 64 + j];
        st[s * 64 + j] = tanhf(acc);
    }
    __syncthreads();

    int s = tid >> 7;
    int o = tid & 127;
    float acc = g1b[o];
    const float* wr = wsm + o * G1W_STRIDE;
    const float* sp = st + s * 64;
#pragma unroll 8
    for (int k = 0; k < 64; k++) acc += wr[k] * sp[k];
    float v = fmaxf(acc, 0.f);
    s_g1h[(b0 + s) * KDIM + o] = __float2half_rn(v);
}

// ========== generator GEMM: pure fp16, single product, 2 CTA/SM ==========
#define A_STRIDE 136
#define AS2      (A_STRIDE * 2)
#define T_BYTES  (128 * AS2)               // 34816
#define OFF_AHI  0
#define OFF_BHI  (T_BYTES)
#define OFF_BIAS (2 * T_BYTES)             // 69632
#define GEMM_SMEM (OFF_BIAS + 512)         // 70144
#define CS_STRIDE 132

__global__ void __launch_bounds__(256, 2) gemm_hmma_k(const float* __restrict__ g2b) {
    extern __shared__ char sm[];
    uint32_t smb = smem_u32(sm);
    int tid = threadIdx.x;
    int wid = tid >> 5, lane = tid & 31;
    int bm = blockIdx.x * 128;
    int bn = blockIdx.y * 128;

    float* bias_sm = (float*)(sm + OFF_BIAS);

    const char* ah = (const char*)(s_g2h + (size_t)bm * KDIM);
    const char* bh = (const char*)(s_g1h + (size_t)bn * KDIM);

#pragma unroll
    for (int i = 0; i < 8; i++) {
        int c = tid + i * 256;
        int row = c >> 4, col = c & 15;
        CP_ASYNC16(smb + OFF_AHI + row * AS2 + col * 16, ah + row * 256 + col * 16);
    }
#pragma unroll
    for (int i = 0; i < 8; i++) {
        int c = tid + i * 256;
        int row = c >> 4, col = c & 15;
        CP_ASYNC16(smb + OFF_BHI + row * AS2 + col * 16, bh + row * 256 + col * 16);
    }
    CP_COMMIT();
    if (tid < 128) {
        int m = bm + tid;
        bias_sm[tid] = (m < TOTAL) ? g2b[m] : 0.f;
    }

    int wm = (wid & 3) * 32;
    int wn = (wid >> 2) * 64;
    int g = lane >> 3, r = lane & 7;
    int a_row = (g & 1) * 8 + r,  a_kof = (g >> 1) * 8;
    int b_row = (g >> 1) * 8 + r, b_kof = (g & 1) * 8;

    float c[16][4];
#pragma unroll
    for (int i = 0; i < 16; i++)
#pragma unroll
        for (int q = 0; q < 4; q++) c[i][q] = 0.f;

    uint32_t a_hi0 = smb + OFF_AHI + (wm + a_row) * AS2 + a_kof * 2;
    uint32_t b_hi0 = smb + OFF_BHI + (wn + b_row) * AS2 + b_kof * 2;

    CP_WAIT(0);
    __syncthreads();
#pragma unroll
    for (int ks = 0; ks < 8; ks++) {
        uint32_t kbyte = ks * 32;
        uint32_t A0[4], A1[4], B[4][4];
        ldsm_x4(a_hi0 + kbyte, A0);
        ldsm_x4(a_hi0 + 16 * AS2 + kbyte, A1);
#pragma unroll
        for (int nb = 0; nb < 4; nb++)
            ldsm_x4(b_hi0 + nb * 16 * AS2 + kbyte, B[nb]);
#pragma unroll
        for (int nb = 0; nb < 4; nb++) {
            mma_f16(c[nb * 2 + 0],     A0, &B[nb][0]);
            mma_f16(c[nb * 2 + 1],     A0, &B[nb][2]);
            mma_f16(c[8 + nb * 2 + 0], A1, &B[nb][0]);
            mma_f16(c[8 + nb * 2 + 1], A1, &B[nb][2]);
        }
    }
    __syncthreads();   // operands dead; reuse smem as C staging

    // ---- stage C -> smem [n][m] transpose, then fp16 coalesced global write ----
    float* Cs = (float*)sm;
    {
        int mr = lane >> 2;
        int nc = (lane & 3) * 2;
#pragma unroll
        for (int mi = 0; mi < 2; mi++) {
#pragma unroll
            for (int ni = 0; ni < 8; ni++) {
                float* cf = c[mi * 8 + ni];
                int m = wm + mi * 16 + mr;
                int n = wn + ni * 8 + nc;
                Cs[(n)     * CS_STRIDE + m]     = cf[0];
                Cs[(n + 1) * CS_STRIDE + m]     = cf[1];
                Cs[(n)     * CS_STRIDE + m + 8] = cf[2];
                Cs[(n + 1) * CS_STRIDE + m + 8] = cf[3];
            }
        }
    }
    __syncthreads();
    {
        int s  = tid >> 1;
        int mh = (tid & 1) * 64;
        __half* dst = s_g + (size_t)(bn + s) * TOTAL_PAD + bm + mh;
        const float* csrc = Cs + s * CS_STRIDE + mh;
        const float* bia  = bias_sm + mh;
#pragma unroll
        for (int i = 0; i < 64; i += 8) {
            float4 v0 = *(const float4*)(csrc + i);
            float4 v1 = *(const float4*)(csrc + i + 4);
            v0.x += bia[i + 0]; v0.y += bia[i + 1];
            v0.z += bia[i + 2]; v0.w += bia[i + 3];
            v1.x += bia[i + 4]; v1.y += bia[i + 5];
            v1.z += bia[i + 6]; v1.w += bia[i + 7];
            __half2 h0 = __floats2half2_rn(v0.x, v0.y);
            __half2 h1 = __floats2half2_rn(v0.z, v0.w);
            __half2 h2 = __floats2half2_rn(v1.x, v1.y);
            __half2 h3 = __floats2half2_rn(v1.z, v1.w);
            uint4 pk;
            pk.x = *(uint32_t*)&h0; pk.y = *(uint32_t*)&h1;
            pk.z = *(uint32_t*)&h2; pk.w = *(uint32_t*)&h3;
            *(uint4*)(dst + i) = pk;
        }
    }
}

// ================= apply: per-sample low-rank MLP (fp16 g) ========
__global__ void apply_k(const float* __restrict__ img, float* __restrict__ out) {
    int b = blockIdx.x;
    __shared__ float4 xs4[196];
    __shared__ float h1[H1];
    __shared__ float t1[RANK];
    __shared__ float t2[RANK];
    int tid = threadIdx.x;
    int warp = tid >> 5, lane = tid & 31;
    const __half* gb = s_g + (size_t)b * TOTAL_PAD;

    if (tid < 196) xs4[tid] = ((const float4*)(img + b * IN_D))[tid];
    __syncthreads();

    // t1[r] = b1f[r] . x (warp r and r+8)
    {
        const __half* bp0 = gb + O_B1 + warp * IN_D;
        const __half* bp1 = gb + O_B1 + (warp + 8) * IN_D;
        float acc0 = 0.f, acc1 = 0.f;
#pragma unroll 7
        for (int i = lane; i < 196; i += 32) {
            float4 x = xs4[i];
            float4 wA = h4_to_f4(*(const uint2*)(bp0 + i * 4));
            float4 wB = h4_to_f4(*(const uint2*)(bp1 + i * 4));
            acc0 += wA.x * x.x + wA.y * x.y + wA.z * x.z + wA.w * x.w;
            acc1 += wB.x * x.x + wB.y * x.y + wB.z * x.z + wB.w * x.w;
        }
#pragma unroll
        for (int o = 16; o > 0; o >>= 1) {
            acc0 += __shfl_xor_sync(0xffffffffu, acc0, o);
            acc1 += __shfl_xor_sync(0xffffffffu, acc1, o);
        }
        if (lane == 0) { t1[warp] = acc0; t1[warp + 8] = acc1; }
    }
    __syncthreads();

    // h1[o] = relu(a1[o] . t1 + bias1[o]), o = tid, tid+256
    {
        const float4* tp = (const float4*)t1;
        float4 t0 = tp[0], t1v = tp[1], t2v = tp[2], t3 = tp[3];
#pragma unroll
        for (int q = 0; q < 2; q++) {
            int o = tid + q * 256;
            const uint2* ap = (const uint2*)(gb + O_A1 + o * RANK);
            float acc = __half2float(gb[O_BIAS1 + o]);
            float4 a0 = h4_to_f4(ap[0]);
            float4 a1 = h4_to_f4(ap[1]);
            float4 a2 = h4_to_f4(ap[2]);
            float4 a3 = h4_to_f4(ap[3]);
            acc += a0.x * t0.x + a0.y * t0.y + a0.z * t0.z + a0.w * t0.w;
            acc += a1.x * t1v.x + a1.y * t1v.y + a1.z * t1v.z + a1.w * t1v.w;
            acc += a2.x * t2v.x + a2.y * t2v.y + a2.z * t2v.z + a2.w * t2v.w;
            acc += a3.x * t3.x + a3.y * t3.y + a3.z * t3.z + a3.w * t3.w;
            h1[o] = fmaxf(acc, 0.f);
        }
    }
    __syncthreads();

    // t2[r] = b2f[r] . h1
    {
        const __half* bp0 = gb + O_B2 + warp * H1;
        const __half* bp1 = gb + O_B2 + (warp + 8) * H1;
        const float4* hp = (const float4*)h1;
        float acc0 = 0.f, acc1 = 0.f;
#pragma unroll
        for (int i = lane; i < 128; i += 32) {
            float4 h = hp[i];
            float4 wA = h4_to_f4(*(const uint2*)(bp0 + i * 4));
            float4 wB = h4_to_f4(*(const uint2*)(bp1 + i * 4));
            acc0 += wA.x * h.x + wA.y * h.y + wA.z * h.z + wA.w * h.w;
            acc1 += wB.x * h.x + wB.y * h.y + wB.z * h.z + wB.w * h.w;
        }
#pragma unroll
        for (int o = 16; o > 0; o >>= 1) {
            acc0 += __shfl_xor_sync(0xffffffffu, acc0, o);
            acc1 += __shfl_xor_sync(0xffffffffu, acc1, o);
        }
        if (lane == 0) { t2[warp] = acc0; t2[warp + 8] = acc1; }
    }
    __syncthreads();

    if (tid < OUT_D) {
        const uint2* ap = (const uint2*)(gb + O_A2 + tid * RANK);
        const float4* tp = (const float4*)t2;
        float acc = __half2float(gb[O_BIAS2 + tid]);
#pragma unroll
        for (int q = 0; q < 4; q++) {
            float4 a = h4_to_f4(ap[q]);
            float4 t = tp[q];
            acc += a.x * t.x + a.y * t.y + a.z * t.z + a.w * t.w;
        }
        out[b * OUT_D + tid] = acc;
    }
}

// ================= launch =================
extern "C" void kernel_launch(void* const* d_in, const int* in_sizes, int n_in,
                              void* d_out, int out_size) {
    const float* images = (const float*)d_in[0];
    const float* c1w    = (const float*)d_in[1];
    const float* c1b    = (const float*)d_in[2];
    const float* c2w    = (const float*)d_in[3];
    const float* c2b    = (const float*)d_in[4];
    const float* sew    = (const float*)d_in[5];
    const float* seb    = (const float*)d_in[6];
    const float* g1w    = (const float*)d_in[7];
    const float* g1b    = (const float*)d_in[8];
    const float* g2w    = (const float*)d_in[9];
    const float* g2b    = (const float*)d_in[10];
    float* out = (float*)d_out;

    cudaFuncSetAttribute(style_part_k, cudaFuncAttributeMaxDynamicSharedMemorySize,
                         STYLE_SMEM);
    cudaFuncSetAttribute(gemm_hmma_k, cudaFuncAttributeMaxDynamicSharedMemorySize,
                         GEMM_SMEM);

    prep_g2w_k<<<(TOTAL_PAD * KDIM / 8 + 255) / 256, 256>>>(g2w);
    conv_fused_k<<<BATCH, 256>>>(images, c1w, c1b, c2w, c2b);
    style_part_k<<<dim3(8, 8), 256, STYLE_SMEM>>>(sew);
    reduce_g1_k<<<BATCH / 2, 256>>>(seb, g1w, g1b);
    gemm_hmma_k<<<dim3(TOTAL_PAD / 128, BATCH / 128), 256, GEMM_SMEM>>>(g2b);
    apply_k<<<BATCH, 256>>>(images, out);
}